// round 15
// baseline (speedup 1.0000x reference)
#include <cuda_runtime.h>
#include <math.h>
#include <stdint.h>

#define BATCH 8
#define CHN 128
#define HH 56
#define WW 56
#define TILE_PTS 32
#define NTHREADS 256
#define NTILES 16384
#define GRID_CTAS 296

#define A_STRIDE 260     // %8==1 -> conflict-free LDSM
#define W1_STRIDE 260

// float-index offsets in dynamic smem
#define FOFF_A     0                          // 32 x 260 = 8320
#define FOFF_W1    (32 * A_STRIDE)            // 64 x 260 = 16640
#define FOFF_MISC  (FOFF_W1 + 64 * W1_STRIDE)
#define MI_B1   0
#define MI_B2   64
#define MI_B3   128
#define MI_W4   192
#define MI_BG   256      // 192 floats
#define MI_PART 448      // 128 floats
#define SMEM_TOTAL ((FOFF_MISC + 640) * 4)    // 102,400 bytes -> 2 CTAs/SM

// ---------------- globals ----------------
__device__ float  g_tf[BATCH * HH * WW * CHN];   // (B,H,W,C) features
__device__ float  g_W1T[64 * W1_STRIDE];         // n-major padded tf32 image
__device__ float2 g_W2f[2048];                   // frag-order: [kk][n8grp][lane]
__device__ float2 g_W3f[2048];

__device__ __forceinline__ float to_tf32(float x) {
    uint32_t r;
    asm("cvt.rna.tf32.f32 %0, %1;" : "=r"(r) : "f"(x));
    return __uint_as_float(r);
}
__device__ __forceinline__ uint32_t smem_u32(const void* p) {
    uint32_t a;
    asm("{ .reg .u64 t; cvta.to.shared.u64 t, %1; cvt.u32.u64 %0, t; }" : "=r"(a) : "l"(p));
    return a;
}
__device__ __forceinline__ void ldsm4(uint32_t* r, uint32_t addr) {
    asm volatile("ldmatrix.sync.aligned.m8n8.x4.shared.b16 {%0,%1,%2,%3}, [%4];"
                 : "=r"(r[0]), "=r"(r[1]), "=r"(r[2]), "=r"(r[3]) : "r"(addr));
}
__device__ __forceinline__ void mma16n8k8(float* d, const uint32_t* a, uint32_t b0, uint32_t b1) {
    asm volatile(
        "mma.sync.aligned.m16n8k8.row.col.f32.tf32.tf32.f32 "
        "{%0,%1,%2,%3}, {%4,%5,%6,%7}, {%8,%9}, {%0,%1,%2,%3};"
        : "+f"(d[0]), "+f"(d[1]), "+f"(d[2]), "+f"(d[3])
        : "r"(a[0]), "r"(a[1]), "r"(a[2]), "r"(a[3]), "r"(b0), "r"(b1));
}
#define FU(x) __float_as_uint(x)

// ---------------------------------------------------------------------------
// Kernel 1: transpose features + prep weight images (merged)
// ---------------------------------------------------------------------------
__global__ void transpose_kernel(const float* __restrict__ f,
                                 const float* __restrict__ W1,
                                 const float* __restrict__ W2,
                                 const float* __restrict__ W3) {
    __shared__ float tile[32][33];
    const int b  = blockIdx.z;
    const int c0 = blockIdx.y << 5;
    const int s0 = blockIdx.x << 5;
    const int tx = threadIdx.x, ty = threadIdx.y;
    tile[ty][tx] = f[(size_t)(b * CHN + c0 + ty) * 3136 + (s0 + tx)];
    __syncthreads();
    g_tf[(size_t)(b * 3136 + s0 + ty) * CHN + (c0 + tx)] = tile[tx][ty];

    if (blockIdx.x == 0 && blockIdx.y == 0) {
        const int t = ty * 32 + tx;
        const int base = b * 1024 + t;          // 0..8191
        for (int i = base; i < 64 * 256; i += 8192) {
            int n = i & 63, k = i >> 6;
            g_W1T[n * W1_STRIDE + k] = to_tf32(W1[k * 64 + n]);
        }
        // frag-order W2/W3: idx = (kk*8 + ng)*32 + lane
        if (base < 2048) {
            const int kk   = base >> 8;
            const int ng   = (base >> 5) & 7;
            const int lane = base & 31;
            const int n = ng * 8 + (lane >> 2);
            const int k = kk * 8 + (lane & 3);
            g_W2f[base] = make_float2(to_tf32(W2[k * 64 + n]), to_tf32(W2[(k + 4) * 64 + n]));
            g_W3f[base] = make_float2(to_tf32(W3[k * 64 + n]), to_tf32(W3[(k + 4) * 64 + n]));
        }
    }
}

// ---------------------------------------------------------------------------
// Kernel 2: persistent decoder — 2 CTAs/SM, 32-point tiles
//   8 warps = 2 mslots (m16) x 4 nslots (n16)
// ---------------------------------------------------------------------------
__global__ __launch_bounds__(NTHREADS, 2)
void decoder_kernel(const float* __restrict__ points,
                    const float* __restrict__ kmat,
                    const float* __restrict__ rtm,
                    const float* __restrict__ Bg,
                    const float* __restrict__ b1,
                    const float* __restrict__ b2,
                    const float* __restrict__ b3,
                    const float* __restrict__ W4,
                    const float* __restrict__ b4,
                    float* __restrict__ out) {
    extern __shared__ float sm[];
    float* sA  = sm + FOFF_A;
    float* sW1 = sm + FOFF_W1;
    float* sMi = sm + FOFF_MISC;
    float* sB1 = sMi + MI_B1;
    float* sB2 = sMi + MI_B2;
    float* sB3 = sMi + MI_B3;
    float* sW4 = sMi + MI_W4;
    float* sBg = sMi + MI_BG;
    float* sPart = sMi + MI_PART;

    const int tid  = threadIdx.x;
    const int wid  = tid >> 5;
    const int lane = tid & 31;

    const int mslot = wid >> 2;       // 0..1
    const int nslot = wid & 3;        // 0..3
    const int g  = lane >> 2;
    const int t  = lane & 3;
    const int ng0 = nslot * 2;        // global n8 groups
    const int ng1 = ng0 + 1;

    const uint32_t sAu  = smem_u32(sA);
    const uint32_t sW1u = smem_u32(sW1);

    // A-frag ldsm address (one m16 tile per warp)
    const int arow = mslot * 16 + (lane & 15);
    const int acol = (lane >> 4) << 2;
    const uint32_t aBase = sAu + (uint32_t)((arow * A_STRIDE + acol) << 2);
    // W1 B-frag address (covers warp's n16 via x4)
    const int nrow = nslot * 16 + ((lane & 16) >> 1) + (lane & 7);
    const int ncol = (lane & 8) ? 4 : 0;
    const uint32_t b1Base = sW1u + (uint32_t)((nrow * W1_STRIDE + ncol) << 2);

    // ---- one-time init ----
    {
        const float4* s = (const float4*)g_W1T;
        float4* d = (float4*)sW1;
        for (int i = tid; i < 64 * W1_STRIDE / 4; i += NTHREADS) d[i] = s[i];
    }
    if (tid < 64) {
        sB1[tid] = b1[tid]; sB2[tid] = b2[tid]; sB3[tid] = b3[tid];
        sW4[tid] = W4[tid];
    }
    if (tid < 96) ((float2*)sBg)[tid] = ((const float2*)Bg)[tid];
    const float b4v = b4[0];
    __syncthreads();

    for (int tile = blockIdx.x; tile < NTILES; tile += GRID_CTAS) {
        const int p0 = tile * TILE_PTS;
        const int b  = tile >> 11;    // 2048 tiles of 32 pts per batch

        // ---- warp-local projection: lanes 0..3 own this warp's 4 points ----
        float fx = 0.f, fy = 0.f, va = 0.f, ppx = 0.f, ppy = 0.f, ppz = 0.f;
        int x0 = -100000, y0 = -100000;
        if (lane < 4) {
            const float* pt = points + (size_t)(p0 + wid * 4 + lane) * 3;
            ppx = pt[0]; ppy = pt[1]; ppz = pt[2];
            const float* R = rtm + b * 12;
            const float* K = kmat + b * 9;
            const float cx = fmaf(R[0], ppx, fmaf(R[1], ppy, fmaf(R[2],  ppz, R[3])));
            const float cy = fmaf(R[4], ppx, fmaf(R[5], ppy, fmaf(R[6],  ppz, R[7])));
            const float cz = fmaf(R[8], ppx, fmaf(R[9], ppy, fmaf(R[10], ppz, R[11])));
            const float ix = fmaf(K[0], cx, fmaf(K[1], cy, K[2] * cz));
            const float iy = fmaf(K[3], cx, fmaf(K[4], cy, K[5] * cz));
            const float iz = fmaf(K[6], cx, fmaf(K[7], cy, K[8] * cz));
            const bool pos = (iz > 0.0f);
            const float zz = iz + 1e-8f;
            const float u = __fdividef(ix, zz), v = __fdividef(iy, zz);
            const float xf = floorf(u), yf = floorf(v);
            fx = u - xf; fy = v - yf;
            x0 = (int)xf; y0 = (int)yf;
            if (!pos) { x0 = -100000; y0 = -100000; fx = 0.f; fy = 0.f; }
            va = pos ? 1.0f : 0.0f;
        }

        // ---- merged gather + Fourier into warp's 4 A rows ----
        {
            const float* baseb = g_tf + (size_t)b * 3136 * CHN + lane * 4;
            const float TWOPI = 6.283185307179586f;
            const float bx0 = sBg[lane * 3],        by0 = sBg[lane * 3 + 1],        bz0 = sBg[lane * 3 + 2];
            const float bx1 = sBg[(lane + 32) * 3], by1 = sBg[(lane + 32) * 3 + 1], bz1 = sBg[(lane + 32) * 3 + 2];
#pragma unroll
            for (int i = 0; i < 4; ++i) {
                const int q = wid * 4 + i;
                const float gfx = __shfl_sync(0xffffffffu, fx, i);
                const float gfy = __shfl_sync(0xffffffffu, fy, i);
                const float gv  = __shfl_sync(0xffffffffu, va, i);
                const int   gx  = __shfl_sync(0xffffffffu, x0, i);
                const int   gy  = __shfl_sync(0xffffffffu, y0, i);
                const float qx  = __shfl_sync(0xffffffffu, ppx, i);
                const float qy  = __shfl_sync(0xffffffffu, ppy, i);
                const float qz  = __shfl_sync(0xffffffffu, ppz, i);

                const float ax = 1.0f - gfx, ay = 1.0f - gfy;
                const float w00 = ax * ay * gv;
                const float w10 = gfx * ay * gv;
                const float w01 = ax * gfy * gv;
                const float w11 = gfx * gfy * gv;
                const bool x0in = (gx >= 0) && (gx < WW);
                const bool x1in = (gx >= -1) && (gx < WW - 1);
                const bool y0in = (gy >= 0) && (gy < HH);
                const bool y1in = (gy >= -1) && (gy < HH - 1);
                const int rowoff = (gy * WW + gx) * CHN;
                float4 a4 = make_float4(0.f, 0.f, 0.f, 0.f);
                if (x0in && y0in) {
                    float4 v4 = *(const float4*)(baseb + rowoff);
                    a4.x = fmaf(w00, v4.x, a4.x); a4.y = fmaf(w00, v4.y, a4.y);
                    a4.z = fmaf(w00, v4.z, a4.z); a4.w = fmaf(w00, v4.w, a4.w);
                }
                if (x1in && y0in) {
                    float4 v4 = *(const float4*)(baseb + rowoff + CHN);
                    a4.x = fmaf(w10, v4.x, a4.x); a4.y = fmaf(w10, v4.y, a4.y);
                    a4.z = fmaf(w10, v4.z, a4.z); a4.w = fmaf(w10, v4.w, a4.w);
                }
                if (x0in && y1in) {
                    float4 v4 = *(const float4*)(baseb + rowoff + WW * CHN);
                    a4.x = fmaf(w01, v4.x, a4.x); a4.y = fmaf(w01, v4.y, a4.y);
                    a4.z = fmaf(w01, v4.z, a4.z); a4.w = fmaf(w01, v4.w, a4.w);
                }
                if (x1in && y1in) {
                    float4 v4 = *(const float4*)(baseb + rowoff + (WW + 1) * CHN);
                    a4.x = fmaf(w11, v4.x, a4.x); a4.y = fmaf(w11, v4.y, a4.y);
                    a4.z = fmaf(w11, v4.z, a4.z); a4.w = fmaf(w11, v4.w, a4.w);
                }

                const float xp0 = TWOPI * fmaf(qx, bx0, fmaf(qy, by0, qz * bz0));
                const float xp1 = TWOPI * fmaf(qx, bx1, fmaf(qy, by1, qz * bz1));
                float* row = sA + q * A_STRIDE;
                row[128 + lane]      = to_tf32(__sinf(xp0));
                row[128 + lane + 32] = to_tf32(__sinf(xp1));
                row[192 + lane]      = to_tf32(__cosf(xp0));
                row[192 + lane + 32] = to_tf32(__cosf(xp1));

                a4.x = to_tf32(a4.x); a4.y = to_tf32(a4.y);
                a4.z = to_tf32(a4.z); a4.w = to_tf32(a4.w);
                *(float4*)(row + lane * 4) = a4;
            }
        }
        __syncthreads();   // A fully built

        // ================= Layer 1 (pipelined): [32x256] @ W1 =================
        float acc[2][4];
#pragma unroll
        for (int nt = 0; nt < 2; ++nt)
#pragma unroll
            for (int j = 0; j < 4; ++j) acc[nt][j] = 0.0f;
        {
            uint32_t aa[2][4], BB[2][4];
            ldsm4(aa[0], aBase);
            ldsm4(BB[0], b1Base);
#pragma unroll 4
            for (int kb = 0; kb < 16; ++kb) {
                const int k1 = 2 * kb + 1;
                ldsm4(aa[1], aBase + k1 * 32);
                ldsm4(BB[1], b1Base + k1 * 32);
                mma16n8k8(acc[0], aa[0], BB[0][0], BB[0][1]);
                mma16n8k8(acc[1], aa[0], BB[0][2], BB[0][3]);
                if (kb < 15) {
                    ldsm4(aa[0], aBase + (k1 + 1) * 32);
                    ldsm4(BB[0], b1Base + (k1 + 1) * 32);
                }
                mma16n8k8(acc[0], aa[1], BB[1][0], BB[1][1]);
                mma16n8k8(acc[1], aa[1], BB[1][2], BB[1][3]);
            }
        }
        __syncthreads();   // L1 A-reads done

        // relu(acc + b1) -> A cols [0,64)
#pragma unroll
        for (int nt = 0; nt < 2; ++nt) {
            const int col = nslot * 16 + nt * 8 + t * 2;
            const int r0 = mslot * 16 + g;
            float2 v0, v1;
            v0.x = to_tf32(fmaxf(acc[nt][0] + sB1[col], 0.f));
            v0.y = to_tf32(fmaxf(acc[nt][1] + sB1[col + 1], 0.f));
            v1.x = to_tf32(fmaxf(acc[nt][2] + sB1[col], 0.f));
            v1.y = to_tf32(fmaxf(acc[nt][3] + sB1[col + 1], 0.f));
            *(float2*)(sA + r0 * A_STRIDE + col) = v0;
            *(float2*)(sA + (r0 + 8) * A_STRIDE + col) = v1;
        }
        __syncthreads();   // h1 ready

        // ================= Layer 2: h1 @ W2 (frag-order global B) ============
#pragma unroll
        for (int nt = 0; nt < 2; ++nt)
#pragma unroll
            for (int j = 0; j < 4; ++j) acc[nt][j] = 0.0f;
        {
            uint32_t aa[2][4];
            float2 bf[2][2];
            ldsm4(aa[0], aBase);
            bf[0][0] = g_W2f[ng0 * 32 + lane];
            bf[0][1] = g_W2f[ng1 * 32 + lane];
#pragma unroll
            for (int kb = 0; kb < 4; ++kb) {
                const int k1 = 2 * kb + 1;
                ldsm4(aa[1], aBase + k1 * 32);
                bf[1][0] = g_W2f[(k1 * 8 + ng0) * 32 + lane];
                bf[1][1] = g_W2f[(k1 * 8 + ng1) * 32 + lane];
                mma16n8k8(acc[0], aa[0], FU(bf[0][0].x), FU(bf[0][0].y));
                mma16n8k8(acc[1], aa[0], FU(bf[0][1].x), FU(bf[0][1].y));
                if (kb < 3) {
                    ldsm4(aa[0], aBase + (k1 + 1) * 32);
                    bf[0][0] = g_W2f[((k1 + 1) * 8 + ng0) * 32 + lane];
                    bf[0][1] = g_W2f[((k1 + 1) * 8 + ng1) * 32 + lane];
                }
                mma16n8k8(acc[0], aa[1], FU(bf[1][0].x), FU(bf[1][0].y));
                mma16n8k8(acc[1], aa[1], FU(bf[1][1].x), FU(bf[1][1].y));
            }
        }
        // relu(acc + b2) -> A cols [64,128)  (disjoint from h1 reads)
#pragma unroll
        for (int nt = 0; nt < 2; ++nt) {
            const int col = nslot * 16 + nt * 8 + t * 2;
            const int r0 = mslot * 16 + g;
            float2 v0, v1;
            v0.x = to_tf32(fmaxf(acc[nt][0] + sB2[col], 0.f));
            v0.y = to_tf32(fmaxf(acc[nt][1] + sB2[col + 1], 0.f));
            v1.x = to_tf32(fmaxf(acc[nt][2] + sB2[col], 0.f));
            v1.y = to_tf32(fmaxf(acc[nt][3] + sB2[col + 1], 0.f));
            *(float2*)(sA + r0 * A_STRIDE + 64 + col) = v0;
            *(float2*)(sA + (r0 + 8) * A_STRIDE + 64 + col) = v1;
        }
        __syncthreads();   // h2 ready

        // ================= Layer 3: h2 @ W3 (frag-order global B) ============
#pragma unroll
        for (int nt = 0; nt < 2; ++nt)
#pragma unroll
            for (int j = 0; j < 4; ++j) acc[nt][j] = 0.0f;
        {
            uint32_t aa[2][4];
            float2 bf[2][2];
            ldsm4(aa[0], aBase + 256);
            bf[0][0] = g_W3f[ng0 * 32 + lane];
            bf[0][1] = g_W3f[ng1 * 32 + lane];
#pragma unroll
            for (int kb = 0; kb < 4; ++kb) {
                const int k1 = 2 * kb + 1;
                ldsm4(aa[1], aBase + 256 + k1 * 32);
                bf[1][0] = g_W3f[(k1 * 8 + ng0) * 32 + lane];
                bf[1][1] = g_W3f[(k1 * 8 + ng1) * 32 + lane];
                mma16n8k8(acc[0], aa[0], FU(bf[0][0].x), FU(bf[0][0].y));
                mma16n8k8(acc[1], aa[0], FU(bf[0][1].x), FU(bf[0][1].y));
                if (kb < 3) {
                    ldsm4(aa[0], aBase + 256 + (k1 + 1) * 32);
                    bf[0][0] = g_W3f[((k1 + 1) * 8 + ng0) * 32 + lane];
                    bf[0][1] = g_W3f[((k1 + 1) * 8 + ng1) * 32 + lane];
                }
                mma16n8k8(acc[0], aa[1], FU(bf[1][0].x), FU(bf[1][0].y));
                mma16n8k8(acc[1], aa[1], FU(bf[1][1].x), FU(bf[1][1].y));
            }
        }

        // ---- layer 4 epilogue ----
        {
            float pr0 = 0.f, pr1 = 0.f;
#pragma unroll
            for (int nt = 0; nt < 2; ++nt) {
                const int col = nslot * 16 + nt * 8 + t * 2;
                pr0 = fmaf(fmaxf(acc[nt][0] + sB3[col], 0.f),     sW4[col],     pr0);
                pr0 = fmaf(fmaxf(acc[nt][1] + sB3[col + 1], 0.f), sW4[col + 1], pr0);
                pr1 = fmaf(fmaxf(acc[nt][2] + sB3[col], 0.f),     sW4[col],     pr1);
                pr1 = fmaf(fmaxf(acc[nt][3] + sB3[col + 1], 0.f), sW4[col + 1], pr1);
            }
            pr0 += __shfl_xor_sync(0xffffffffu, pr0, 1);
            pr0 += __shfl_xor_sync(0xffffffffu, pr0, 2);
            pr1 += __shfl_xor_sync(0xffffffffu, pr1, 1);
            pr1 += __shfl_xor_sync(0xffffffffu, pr1, 2);
            if (t == 0) {
                const int r0 = mslot * 16 + g;
                sPart[nslot * 32 + r0] = pr0;
                sPart[nslot * 32 + r0 + 8] = pr1;
            }
        }
        __syncthreads();   // sPart ready; all L3 A-reads done
        if (tid < 32)
            out[p0 + tid] = sPart[tid] + sPart[32 + tid] + sPart[64 + tid]
                          + sPart[96 + tid] + b4v;
    }
}

// ---------------------------------------------------------------------------
// Launch
// ---------------------------------------------------------------------------
extern "C" void kernel_launch(void* const* d_in, const int* in_sizes, int n_in,
                              void* d_out, int out_size) {
    const float* features = (const float*)d_in[0];
    const float* points   = (const float*)d_in[1];
    const float* kmat     = (const float*)d_in[2];
    const float* rtm      = (const float*)d_in[3];
    const float* Bg       = (const float*)d_in[4];
    const float* W1 = (const float*)d_in[5];
    const float* b1 = (const float*)d_in[6];
    const float* W2 = (const float*)d_in[7];
    const float* b2 = (const float*)d_in[8];
    const float* W3 = (const float*)d_in[9];
    const float* b3 = (const float*)d_in[10];
    const float* W4 = (const float*)d_in[11];
    const float* b4 = (const float*)d_in[12];

    dim3 tb(32, 32);
    dim3 tg(3136 / 32, CHN / 32, BATCH);
    transpose_kernel<<<tg, tb>>>(features, W1, W2, W3);

    cudaFuncSetAttribute(decoder_kernel,
                         cudaFuncAttributeMaxDynamicSharedMemorySize, SMEM_TOTAL);
    decoder_kernel<<<GRID_CTAS, NTHREADS, SMEM_TOTAL>>>(
        points, kmat, rtm, Bg, b1, b2, b3, W4, b4, (float*)d_out);
}

// round 16
// speedup vs baseline: 1.2560x; 1.2560x over previous
#include <cuda_runtime.h>
#include <math.h>
#include <stdint.h>

#define BATCH 8
#define CHN 128
#define HH 56
#define WW 56
#define TILE_PTS 128
#define NTHREADS 256
#define NTILES 4096
#define GRID_CTAS 148

#define A_STRIDE 260     // %8==1 -> conflict-free LDSM
#define W1_STRIDE 260
#define WST 68           // W2 temp stage stride

// float-index offsets in dynamic smem
#define FOFF_A     0                          // 128 x 260
#define FOFF_W1    (128 * A_STRIDE)           // 64 x 260
#define FOFF_MISC  (FOFF_W1 + 64 * W1_STRIDE)
#define MI_B1   0
#define MI_B2   64
#define MI_B3   128
#define MI_W4   192
#define MI_BG   256      // 192 floats
#define SMEM_TOTAL ((FOFF_MISC + 512) * 4)    // 201,728 bytes

#define GBAR() asm volatile("bar.sync %0, 128;" :: "r"(grp + 1) : "memory")

// ---------------- globals ----------------
__device__ float  g_tf[BATCH * HH * WW * CHN];   // (B,H,W,C) features
__device__ float  g_W1T[64 * W1_STRIDE];         // n-major padded tf32 image
__device__ float  g_W2Tc[64 * 64];               // compact n-major tf32 (reg-hoist src)
__device__ float2 g_W3f[2048];                   // frag-order: [kk][ng][lane]

__device__ __forceinline__ float to_tf32(float x) {
    uint32_t r;
    asm("cvt.rna.tf32.f32 %0, %1;" : "=r"(r) : "f"(x));
    return __uint_as_float(r);
}
__device__ __forceinline__ uint32_t smem_u32(const void* p) {
    uint32_t a;
    asm("{ .reg .u64 t; cvta.to.shared.u64 t, %1; cvt.u32.u64 %0, t; }" : "=r"(a) : "l"(p));
    return a;
}
__device__ __forceinline__ void ldsm4(uint32_t* r, uint32_t addr) {
    asm volatile("ldmatrix.sync.aligned.m8n8.x4.shared.b16 {%0,%1,%2,%3}, [%4];"
                 : "=r"(r[0]), "=r"(r[1]), "=r"(r[2]), "=r"(r[3]) : "r"(addr));
}
__device__ __forceinline__ void mma16n8k8(float* d, const uint32_t* a, uint32_t b0, uint32_t b1) {
    asm volatile(
        "mma.sync.aligned.m16n8k8.row.col.f32.tf32.tf32.f32 "
        "{%0,%1,%2,%3}, {%4,%5,%6,%7}, {%8,%9}, {%0,%1,%2,%3};"
        : "+f"(d[0]), "+f"(d[1]), "+f"(d[2]), "+f"(d[3])
        : "r"(a[0]), "r"(a[1]), "r"(a[2]), "r"(a[3]), "r"(b0), "r"(b1));
}
#define FU(x) __float_as_uint(x)

struct Proj { float fx, fy, va, px, py, pz; int x0, y0; };

// ---------------------------------------------------------------------------
// Kernel 1: transpose features + prep weight images (merged)
// ---------------------------------------------------------------------------
__global__ void transpose_kernel(const float* __restrict__ f,
                                 const float* __restrict__ W1,
                                 const float* __restrict__ W2,
                                 const float* __restrict__ W3) {
    __shared__ float tile[32][33];
    const int b  = blockIdx.z;
    const int c0 = blockIdx.y << 5;
    const int s0 = blockIdx.x << 5;
    const int tx = threadIdx.x, ty = threadIdx.y;
    tile[ty][tx] = f[(size_t)(b * CHN + c0 + ty) * 3136 + (s0 + tx)];
    __syncthreads();
    g_tf[(size_t)(b * 3136 + s0 + ty) * CHN + (c0 + tx)] = tile[tx][ty];

    if (blockIdx.x == 0 && blockIdx.y == 0) {
        const int t = ty * 32 + tx;
        const int base = b * 1024 + t;          // 0..8191
        for (int i = base; i < 64 * 256; i += 8192) {
            int n = i & 63, k = i >> 6;
            g_W1T[n * W1_STRIDE + k] = to_tf32(W1[k * 64 + n]);
        }
        for (int i = base; i < 64 * 64; i += 8192) {
            int n = i & 63, k = i >> 6;
            g_W2Tc[n * 64 + k] = to_tf32(W2[k * 64 + n]);
        }
        if (base < 2048) {
            const int kk   = base >> 8;
            const int ng   = (base >> 5) & 7;
            const int lane = base & 31;
            const int n = ng * 8 + (lane >> 2);
            const int k = kk * 8 + (lane & 3);
            g_W3f[base] = make_float2(to_tf32(W3[k * 64 + n]), to_tf32(W3[(k + 4) * 64 + n]));
        }
    }
}

// ---------------------------------------------------------------------------
__device__ __forceinline__ void do_proj(const float* __restrict__ points,
                                        const float* __restrict__ kmat,
                                        const float* __restrict__ rtm,
                                        int pbase, int b, int lane, Proj& P) {
    if (lane < 16) {
        const float* pt = points + (size_t)(pbase + lane) * 3;
        P.px = pt[0]; P.py = pt[1]; P.pz = pt[2];
        const float* R = rtm + b * 12;
        const float* K = kmat + b * 9;
        const float cx = fmaf(R[0], P.px, fmaf(R[1], P.py, fmaf(R[2],  P.pz, R[3])));
        const float cy = fmaf(R[4], P.px, fmaf(R[5], P.py, fmaf(R[6],  P.pz, R[7])));
        const float cz = fmaf(R[8], P.px, fmaf(R[9], P.py, fmaf(R[10], P.pz, R[11])));
        const float ix = fmaf(K[0], cx, fmaf(K[1], cy, K[2] * cz));
        const float iy = fmaf(K[3], cx, fmaf(K[4], cy, K[5] * cz));
        const float iz = fmaf(K[6], cx, fmaf(K[7], cy, K[8] * cz));
        const bool pos = (iz > 0.0f);
        const float zz = iz + 1e-8f;
        const float u = __fdividef(ix, zz), v = __fdividef(iy, zz);
        const float xf = floorf(u), yf = floorf(v);
        P.fx = u - xf; P.fy = v - yf;
        P.x0 = (int)xf; P.y0 = (int)yf;
        if (!pos) { P.x0 = -100000; P.y0 = -100000; P.fx = 0.f; P.fy = 0.f; }
        P.va = pos ? 1.0f : 0.0f;
    }
}

__device__ __forceinline__ void do_gather_fourier(const Proj& P,
                                                  const float* __restrict__ sBg,
                                                  float* __restrict__ sA,
                                                  const float* __restrict__ baseb,
                                                  int q0, int lane) {
    const float TWOPI = 6.283185307179586f;
    const float bx0 = sBg[lane * 3],        by0 = sBg[lane * 3 + 1],        bz0 = sBg[lane * 3 + 2];
    const float bx1 = sBg[(lane + 32) * 3], by1 = sBg[(lane + 32) * 3 + 1], bz1 = sBg[(lane + 32) * 3 + 2];
#pragma unroll 4
    for (int i = 0; i < 16; ++i) {
        const int q = q0 + i;
        const float gfx = __shfl_sync(0xffffffffu, P.fx, i);
        const float gfy = __shfl_sync(0xffffffffu, P.fy, i);
        const float gv  = __shfl_sync(0xffffffffu, P.va, i);
        const int   gx  = __shfl_sync(0xffffffffu, P.x0, i);
        const int   gy  = __shfl_sync(0xffffffffu, P.y0, i);
        const float qx  = __shfl_sync(0xffffffffu, P.px, i);
        const float qy  = __shfl_sync(0xffffffffu, P.py, i);
        const float qz  = __shfl_sync(0xffffffffu, P.pz, i);

        const float ax = 1.0f - gfx, ay = 1.0f - gfy;
        const float w00 = ax * ay * gv;
        const float w10 = gfx * ay * gv;
        const float w01 = ax * gfy * gv;
        const float w11 = gfx * gfy * gv;
        const bool x0in = (gx >= 0) && (gx < WW);
        const bool x1in = (gx >= -1) && (gx < WW - 1);
        const bool y0in = (gy >= 0) && (gy < HH);
        const bool y1in = (gy >= -1) && (gy < HH - 1);
        const int rowoff = (gy * WW + gx) * CHN;
        float4 a4 = make_float4(0.f, 0.f, 0.f, 0.f);
        if (x0in && y0in) {
            float4 v4 = *(const float4*)(baseb + rowoff);
            a4.x = fmaf(w00, v4.x, a4.x); a4.y = fmaf(w00, v4.y, a4.y);
            a4.z = fmaf(w00, v4.z, a4.z); a4.w = fmaf(w00, v4.w, a4.w);
        }
        if (x1in && y0in) {
            float4 v4 = *(const float4*)(baseb + rowoff + CHN);
            a4.x = fmaf(w10, v4.x, a4.x); a4.y = fmaf(w10, v4.y, a4.y);
            a4.z = fmaf(w10, v4.z, a4.z); a4.w = fmaf(w10, v4.w, a4.w);
        }
        if (x0in && y1in) {
            float4 v4 = *(const float4*)(baseb + rowoff + WW * CHN);
            a4.x = fmaf(w01, v4.x, a4.x); a4.y = fmaf(w01, v4.y, a4.y);
            a4.z = fmaf(w01, v4.z, a4.z); a4.w = fmaf(w01, v4.w, a4.w);
        }
        if (x1in && y1in) {
            float4 v4 = *(const float4*)(baseb + rowoff + (WW + 1) * CHN);
            a4.x = fmaf(w11, v4.x, a4.x); a4.y = fmaf(w11, v4.y, a4.y);
            a4.z = fmaf(w11, v4.z, a4.z); a4.w = fmaf(w11, v4.w, a4.w);
        }

        const float xp0 = TWOPI * fmaf(qx, bx0, fmaf(qy, by0, qz * bz0));
        const float xp1 = TWOPI * fmaf(qx, bx1, fmaf(qy, by1, qz * bz1));
        float* row = sA + q * A_STRIDE;
        row[128 + lane]      = to_tf32(__sinf(xp0));
        row[128 + lane + 32] = to_tf32(__sinf(xp1));
        row[192 + lane]      = to_tf32(__cosf(xp0));
        row[192 + lane + 32] = to_tf32(__cosf(xp1));

        a4.x = to_tf32(a4.x); a4.y = to_tf32(a4.y);
        a4.z = to_tf32(a4.z); a4.w = to_tf32(a4.w);
        *(float4*)(row + lane * 4) = a4;
    }
}

// ---------------------------------------------------------------------------
// Kernel 2: persistent fused decoder — 2 groups x 4 warps, pipelined tiles
// ---------------------------------------------------------------------------
__global__ __launch_bounds__(NTHREADS, 1)
void decoder_kernel(const float* __restrict__ points,
                    const float* __restrict__ kmat,
                    const float* __restrict__ rtm,
                    const float* __restrict__ Bg,
                    const float* __restrict__ b1,
                    const float* __restrict__ b2,
                    const float* __restrict__ b3,
                    const float* __restrict__ W4,
                    const float* __restrict__ b4,
                    float* __restrict__ out) {
    extern __shared__ float sm[];
    float* sA  = sm + FOFF_A;
    float* sW1 = sm + FOFF_W1;
    float* sMi = sm + FOFF_MISC;
    float* sB1 = sMi + MI_B1;
    float* sB2 = sMi + MI_B2;
    float* sB3 = sMi + MI_B3;
    float* sW4 = sMi + MI_W4;
    float* sBg = sMi + MI_BG;

    const int tid  = threadIdx.x;
    const int wid  = tid >> 5;
    const int lane = tid & 31;

    const int grp = wid >> 2;         // 0..1
    const int gw  = wid & 3;          // 0..3
    const int mslot = gw >> 1;        // L1/L2 decomposition
    const int nslot = gw & 1;
    const int g  = lane >> 2;
    const int t  = lane & 3;
    const int q0 = grp * 64 + gw * 16;   // warp's 16 points

    const uint32_t sAu  = smem_u32(sA);
    const uint32_t sW1u = smem_u32(sW1);

    // L1/L2 A-frag addresses (Mw=32)
    const int arow = grp * 64 + mslot * 32 + (lane & 15);
    const int acol = (lane >> 4) << 2;
    const uint32_t aBase0 = sAu + (uint32_t)((arow * A_STRIDE + acol) << 2);
    const uint32_t aBase1 = aBase0 + (uint32_t)(16 * A_STRIDE * 4);
    // W1 B-frag addresses
    const int nrow = nslot * 32 + ((lane & 16) >> 1) + (lane & 7);
    const int ncol = (lane & 8) ? 4 : 0;
    const uint32_t b1Base0 = sW1u + (uint32_t)((nrow * W1_STRIDE + ncol) << 2);
    const uint32_t b1Base1 = b1Base0 + (uint32_t)(16 * W1_STRIDE * 4);
    // L3' A-frag address (Mw=16, rows grp*64+gw*16, cols [64,128))
    const uint32_t aBase3 = sAu +
        (uint32_t)(((grp * 64 + gw * 16 + (lane & 15)) * A_STRIDE + 64 + acol) << 2);

    // ---- one-time init ----
    {
        const float4* s = (const float4*)g_W1T;
        float4* d = (float4*)sW1;
        for (int i = tid; i < 64 * W1_STRIDE / 4; i += NTHREADS) d[i] = s[i];
    }
    for (int i = tid; i < 64 * 64; i += NTHREADS) {      // temp W2 stage in sA
        int n = i >> 6, k = i & 63;
        sA[n * WST + k] = g_W2Tc[i];
    }
    if (tid < 64) {
        sB1[tid] = b1[tid]; sB2[tid] = b2[tid]; sB3[tid] = b3[tid];
        sW4[tid] = W4[tid];
    }
    if (tid < 96) ((float2*)sBg)[tid] = ((const float2*)Bg)[tid];
    const float b4v = b4[0];
    __syncthreads();

    // hoist W2 B-fragments to registers (L1/L2 n-mapping)
    uint32_t B2f[64];
    {
        const uint32_t wBase0 = sAu + (uint32_t)((nrow * WST + ncol) << 2);
        const uint32_t wBase1 = wBase0 + (uint32_t)(16 * WST * 4);
#pragma unroll
        for (int kk = 0; kk < 8; ++kk) {
            ldsm4(B2f + kk * 8,     wBase0 + kk * 32);
            ldsm4(B2f + kk * 8 + 4, wBase1 + kk * 32);
        }
    }
    __syncthreads();   // stage reads done before gather overwrites sA

    // ---- prologue: first tile's projection + A-build ----
    int tile = blockIdx.x;
    Proj P;
    {
        const int b0 = (tile * TILE_PTS) >> 16;
        do_proj(points, kmat, rtm, tile * TILE_PTS + q0, b0, lane, P);
        do_gather_fourier(P, sBg, sA, g_tf + (size_t)b0 * 3136 * CHN + lane * 4, q0, lane);
    }

    while (true) {
        const int p0 = tile * TILE_PTS;
        GBAR();   // A ready

        // ================= Layer 1 (pipelined): [64x256] @ W1 =================
        float acc[2][4][4];
#pragma unroll
        for (int mt = 0; mt < 2; ++mt)
#pragma unroll
            for (int nt = 0; nt < 4; ++nt)
#pragma unroll
                for (int j = 0; j < 4; ++j) acc[mt][nt][j] = 0.0f;
        {
            uint32_t aa0[2][4], aa1[2][4], BB[2][8];
            ldsm4(aa0[0], aBase0);
            ldsm4(aa1[0], aBase1);
            ldsm4(BB[0],     b1Base0);
            ldsm4(BB[0] + 4, b1Base1);
#pragma unroll 2
            for (int kb = 0; kb < 16; ++kb) {
                const int k1 = 2 * kb + 1;
                ldsm4(aa0[1], aBase0 + k1 * 32);
                ldsm4(aa1[1], aBase1 + k1 * 32);
                ldsm4(BB[1],     b1Base0 + k1 * 32);
                ldsm4(BB[1] + 4, b1Base1 + k1 * 32);
#pragma unroll
                for (int nt = 0; nt < 4; ++nt) {
                    mma16n8k8(acc[0][nt], aa0[0], BB[0][nt * 2], BB[0][nt * 2 + 1]);
                    mma16n8k8(acc[1][nt], aa1[0], BB[0][nt * 2], BB[0][nt * 2 + 1]);
                }
                if (kb < 15) {
                    ldsm4(aa0[0], aBase0 + (k1 + 1) * 32);
                    ldsm4(aa1[0], aBase1 + (k1 + 1) * 32);
                    ldsm4(BB[0],     b1Base0 + (k1 + 1) * 32);
                    ldsm4(BB[0] + 4, b1Base1 + (k1 + 1) * 32);
                }
#pragma unroll
                for (int nt = 0; nt < 4; ++nt) {
                    mma16n8k8(acc[0][nt], aa0[1], BB[1][nt * 2], BB[1][nt * 2 + 1]);
                    mma16n8k8(acc[1][nt], aa1[1], BB[1][nt * 2], BB[1][nt * 2 + 1]);
                }
            }
        }
        GBAR();   // L1 A-reads done

        // relu(acc + b1) -> A cols [0,64)
#pragma unroll
        for (int mt = 0; mt < 2; ++mt) {
            const int r0 = grp * 64 + mslot * 32 + mt * 16 + g;
#pragma unroll
            for (int nt = 0; nt < 4; ++nt) {
                const int col = nslot * 32 + nt * 8 + t * 2;
                float2 v0, v1;
                v0.x = to_tf32(fmaxf(acc[mt][nt][0] + sB1[col], 0.f));
                v0.y = to_tf32(fmaxf(acc[mt][nt][1] + sB1[col + 1], 0.f));
                v1.x = to_tf32(fmaxf(acc[mt][nt][2] + sB1[col], 0.f));
                v1.y = to_tf32(fmaxf(acc[mt][nt][3] + sB1[col + 1], 0.f));
                *(float2*)(sA + r0 * A_STRIDE + col) = v0;
                *(float2*)(sA + (r0 + 8) * A_STRIDE + col) = v1;
            }
        }
        GBAR();   // h1 ready

        // ================= Layer 2 (pipelined A): h1 @ W2, B in regs =========
#pragma unroll
        for (int mt = 0; mt < 2; ++mt)
#pragma unroll
            for (int nt = 0; nt < 4; ++nt)
#pragma unroll
                for (int j = 0; j < 4; ++j) acc[mt][nt][j] = 0.0f;
        {
            uint32_t aa0[2][4], aa1[2][4];
            ldsm4(aa0[0], aBase0);
            ldsm4(aa1[0], aBase1);
#pragma unroll
            for (int kb = 0; kb < 4; ++kb) {
                const int k1 = 2 * kb + 1;
                ldsm4(aa0[1], aBase0 + k1 * 32);
                ldsm4(aa1[1], aBase1 + k1 * 32);
#pragma unroll
                for (int nt = 0; nt < 4; ++nt) {
                    mma16n8k8(acc[0][nt], aa0[0], B2f[(k1 - 1) * 8 + nt * 2], B2f[(k1 - 1) * 8 + nt * 2 + 1]);
                    mma16n8k8(acc[1][nt], aa1[0], B2f[(k1 - 1) * 8 + nt * 2], B2f[(k1 - 1) * 8 + nt * 2 + 1]);
                }
                if (kb < 3) {
                    ldsm4(aa0[0], aBase0 + (k1 + 1) * 32);
                    ldsm4(aa1[0], aBase1 + (k1 + 1) * 32);
                }
#pragma unroll
                for (int nt = 0; nt < 4; ++nt) {
                    mma16n8k8(acc[0][nt], aa0[1], B2f[k1 * 8 + nt * 2], B2f[k1 * 8 + nt * 2 + 1]);
                    mma16n8k8(acc[1][nt], aa1[1], B2f[k1 * 8 + nt * 2], B2f[k1 * 8 + nt * 2 + 1]);
                }
            }
        }
        // relu(acc + b2) -> A cols [64,128)  (disjoint from h1 reads)
#pragma unroll
        for (int mt = 0; mt < 2; ++mt) {
            const int r0 = grp * 64 + mslot * 32 + mt * 16 + g;
#pragma unroll
            for (int nt = 0; nt < 4; ++nt) {
                const int col = nslot * 32 + nt * 8 + t * 2;
                float2 v0, v1;
                v0.x = to_tf32(fmaxf(acc[mt][nt][0] + sB2[col], 0.f));
                v0.y = to_tf32(fmaxf(acc[mt][nt][1] + sB2[col + 1], 0.f));
                v1.x = to_tf32(fmaxf(acc[mt][nt][2] + sB2[col], 0.f));
                v1.y = to_tf32(fmaxf(acc[mt][nt][3] + sB2[col + 1], 0.f));
                *(float2*)(sA + r0 * A_STRIDE + 64 + col) = v0;
                *(float2*)(sA + (r0 + 8) * A_STRIDE + 64 + col) = v1;
            }
        }
        GBAR();   // h2 ready

        // ========== Layer 3': Mw=16, Nw=64 per warp (W3 frags from global) ===
        float acc3[8][4];
#pragma unroll
        for (int nt = 0; nt < 8; ++nt)
#pragma unroll
            for (int j = 0; j < 4; ++j) acc3[nt][j] = 0.0f;
        {
            uint32_t a3[2][4];
            float2 bf3[2][8];
            ldsm4(a3[0], aBase3);
#pragma unroll
            for (int nt = 0; nt < 8; ++nt) bf3[0][nt] = g_W3f[nt * 32 + lane];
#pragma unroll
            for (int kb = 0; kb < 4; ++kb) {
                const int k1 = 2 * kb + 1;
                ldsm4(a3[1], aBase3 + k1 * 32);
#pragma unroll
                for (int nt = 0; nt < 8; ++nt) bf3[1][nt] = g_W3f[(k1 * 8 + nt) * 32 + lane];
#pragma unroll
                for (int nt = 0; nt < 8; ++nt)
                    mma16n8k8(acc3[nt], a3[0], FU(bf3[0][nt].x), FU(bf3[0][nt].y));
                if (kb < 3) {
                    ldsm4(a3[0], aBase3 + (k1 + 1) * 32);
#pragma unroll
                    for (int nt = 0; nt < 8; ++nt) bf3[0][nt] = g_W3f[((k1 + 1) * 8 + nt) * 32 + lane];
                }
#pragma unroll
                for (int nt = 0; nt < 8; ++nt)
                    mma16n8k8(acc3[nt], a3[1], FU(bf3[1][nt].x), FU(bf3[1][nt].y));
            }
        }

        // ---- hoisted projection for next tile (hides under barrier) ----
        const int nxt = tile + GRID_CTAS;
        const bool more = (nxt < NTILES);
        if (more) {
            const int nb = (nxt * TILE_PTS) >> 16;
            do_proj(points, kmat, rtm, nxt * TILE_PTS + q0, nb, lane, P);
        }
        GBAR();   // L3' A-reads done

        // ---- layer 4 epilogue: in-warp reduction, direct STG ----
        {
            float pr0 = 0.f, pr1 = 0.f;
#pragma unroll
            for (int nt = 0; nt < 8; ++nt) {
                const int col = nt * 8 + t * 2;
                pr0 = fmaf(fmaxf(acc3[nt][0] + sB3[col], 0.f),     sW4[col],     pr0);
                pr0 = fmaf(fmaxf(acc3[nt][1] + sB3[col + 1], 0.f), sW4[col + 1], pr0);
                pr1 = fmaf(fmaxf(acc3[nt][2] + sB3[col], 0.f),     sW4[col],     pr1);
                pr1 = fmaf(fmaxf(acc3[nt][3] + sB3[col + 1], 0.f), sW4[col + 1], pr1);
            }
            pr0 += __shfl_xor_sync(0xffffffffu, pr0, 1);
            pr0 += __shfl_xor_sync(0xffffffffu, pr0, 2);
            pr1 += __shfl_xor_sync(0xffffffffu, pr1, 1);
            pr1 += __shfl_xor_sync(0xffffffffu, pr1, 2);
            if (t == 0) {
                out[p0 + q0 + g]     = pr0 + b4v;
                out[p0 + q0 + g + 8] = pr1 + b4v;
            }
        }

        // ---- next tile's A-build ----
        if (!more) break;
        {
            const int nb = (nxt * TILE_PTS) >> 16;
            do_gather_fourier(P, sBg, sA, g_tf + (size_t)nb * 3136 * CHN + lane * 4, q0, lane);
        }
        tile = nxt;
    }
}

// ---------------------------------------------------------------------------
// Launch
// ---------------------------------------------------------------------------
extern "C" void kernel_launch(void* const* d_in, const int* in_sizes, int n_in,
                              void* d_out, int out_size) {
    const float* features = (const float*)d_in[0];
    const float* points   = (const float*)d_in[1];
    const float* kmat     = (const float*)d_in[2];
    const float* rtm      = (const float*)d_in[3];
    const float* Bg       = (const float*)d_in[4];
    const float* W1 = (const float*)d_in[5];
    const float* b1 = (const float*)d_in[6];
    const float* W2 = (const float*)d_in[7];
    const float* b2 = (const float*)d_in[8];
    const float* W3 = (const float*)d_in[9];
    const float* b3 = (const float*)d_in[10];
    const float* W4 = (const float*)d_in[11];
    const float* b4 = (const float*)d_in[12];

    dim3 tb(32, 32);
    dim3 tg(3136 / 32, CHN / 32, BATCH);
    transpose_kernel<<<tg, tb>>>(features, W1, W2, W3);

    cudaFuncSetAttribute(decoder_kernel,
                         cudaFuncAttributeMaxDynamicSharedMemorySize, SMEM_TOTAL);
    decoder_kernel<<<GRID_CTAS, NTHREADS, SMEM_TOTAL>>>(
        points, kmat, rtm, Bg, b1, b2, b3, W4, b4, (float*)d_out);
}